// round 15
// baseline (speedup 1.0000x reference)
#include <cuda_runtime.h>
#include <cuda_fp16.h>
#include <cstdint>

#define HH   768
#define WW   768
#define HID  256
#define NPIX (HH*WW)

// ---------------- scratch ----------------
__device__ uint32_t g_hxh[HH * 128];
__device__ uint32_t g_hyh[WW * 128];
__device__ float    g_part[2][3 * NPIX];

// ---------------- helpers ----------------
__device__ __forceinline__ uint32_t pack_h2(float lo, float hi) {
    __half2 h = __floats2half2_rn(lo, hi);
    return *reinterpret_cast<uint32_t*>(&h);
}
__device__ __forceinline__ uint32_t hmul2u(uint32_t a, uint32_t b) {
    uint32_t d;
    asm("mul.f16x2 %0, %1, %2;" : "=r"(d) : "r"(a), "r"(b));
    return d;
}
__device__ __forceinline__ float fast_sin(float x) {
    const float INV_PI = 0.3183098861837907f;
    const float PI_HI  = 3.14159274101257324f;
    const float PI_LO  = -8.742277657347586e-8f;
    int   iq = __float2int_rn(x * INV_PI);
    float fq = (float)iq;
    float r  = fmaf(fq, -PI_HI, x);
    r        = fmaf(fq, -PI_LO, r);
    float r2 = r * r;
    float p  = fmaf(r2, 2.7183114939898219e-6f, -1.9839334836096632e-4f);
    p        = fmaf(r2, p, 8.3333293858894632e-3f);
    p        = fmaf(r2, p, -1.6666666641626524e-1f);
    p        = fmaf(r2 * r, p, r);
    return (iq & 1) ? -p : p;
}

#define MMA_F16(d, a, b0, b1) \
    asm volatile("mma.sync.aligned.m16n8k16.row.col.f32.f16.f16.f32 " \
        "{%0,%1,%2,%3}, {%4,%5,%6,%7}, {%8,%9}, {%0,%1,%2,%3};" \
        : "+f"((d)[0]), "+f"((d)[1]), "+f"((d)[2]), "+f"((d)[3]) \
        : "r"((a)[0]), "r"((a)[1]), "r"((a)[2]), "r"((a)[3]), \
          "r"(b0), "r"(b1))

// ---------------------------------------------------------------------------
// branch networks: 12 rows/block, 256 threads, grid (64, 2). unroll 8.
// ---------------------------------------------------------------------------
__global__ __launch_bounds__(256)
void branch_kernel(const float* __restrict__ x, const float* __restrict__ y,
                   const float* __restrict__ Wbx, const float* __restrict__ bbx,
                   const float* __restrict__ Wby, const float* __restrict__ bby,
                   const float* __restrict__ Wp1, const float* __restrict__ bp1,
                   const float* __restrict__ Wp2, const float* __restrict__ bp2)
{
    __shared__ float s0[12 * 256];
    __shared__ float s1[12 * 256];

    const int t  = threadIdx.x;
    const int br = blockIdx.y;
    const float* coord = br ? y   : x;
    const float* Wb    = br ? Wby : Wbx;
    const float* bb    = br ? bby : bbx;
    uint32_t*    outph = br ? g_hyh : g_hxh;
    const int r0 = blockIdx.x * 12;

    {
        float wv = Wb[t], bv = bb[t];
        #pragma unroll
        for (int r = 0; r < 12; r++)
            s0[r * 256 + t] = fast_sin(fmaf(coord[r0 + r], wv, bv));
    }
    __syncthreads();

    {
        float acc[12]; float b = bp1[t];
        #pragma unroll
        for (int r = 0; r < 12; r++) acc[r] = b;
        const float4* wrow = (const float4*)(Wp1 + (size_t)t * HID);
        #pragma unroll 8
        for (int k4 = 0; k4 < 64; k4++) {
            float4 w = wrow[k4];
            #pragma unroll
            for (int r = 0; r < 12; r++) {
                float4 h = *(const float4*)&s0[r * 256 + k4 * 4];
                acc[r] = fmaf(w.x, h.x, acc[r]); acc[r] = fmaf(w.y, h.y, acc[r]);
                acc[r] = fmaf(w.z, h.z, acc[r]); acc[r] = fmaf(w.w, h.w, acc[r]);
            }
        }
        #pragma unroll
        for (int r = 0; r < 12; r++) s1[r * 256 + t] = fast_sin(acc[r]);
    }
    __syncthreads();

    {
        float acc0[12], acc1[12];
        float b0 = bp2[t], b1 = bp2[t + 256];
        #pragma unroll
        for (int r = 0; r < 12; r++) { acc0[r] = b0; acc1[r] = b1; }
        const float4* w0row = (const float4*)(Wp2 + (size_t)t * HID);
        const float4* w1row = (const float4*)(Wp2 + (size_t)(t + 256) * HID);
        #pragma unroll 8
        for (int k4 = 0; k4 < 64; k4++) {
            float4 w0 = w0row[k4], w1 = w1row[k4];
            #pragma unroll
            for (int r = 0; r < 12; r++) {
                float4 h = *(const float4*)&s1[r * 256 + k4 * 4];
                acc0[r] = fmaf(w0.x, h.x, acc0[r]); acc0[r] = fmaf(w0.y, h.y, acc0[r]);
                acc0[r] = fmaf(w0.z, h.z, acc0[r]); acc0[r] = fmaf(w0.w, h.w, acc0[r]);
                acc1[r] = fmaf(w1.x, h.x, acc1[r]); acc1[r] = fmaf(w1.y, h.y, acc1[r]);
                acc1[r] = fmaf(w1.w, h.w, acc1[r]); acc1[r] = fmaf(w1.z, h.z, acc1[r]);
            }
        }
        #pragma unroll
        for (int r = 0; r < 12; r++)
            s0[r * 256 + t] = fast_sin(acc0[r]) + fast_sin(acc1[r]);
    }
    __syncthreads();

    for (int idx = t; idx < 12 * 64; idx += 256) {
        const int r = idx >> 6, s = idx & 63;
        const int n0 = (s >> 2) * 16 + (s & 3) * 2;
        const float* row = s0 + r * 256;
        uint2 val;
        val.x = pack_h2(row[n0],     row[n0 + 1]);
        val.y = pack_h2(row[n0 + 8], row[n0 + 9]);
        ((uint2*)outph)[(size_t)(r0 + r) * 64 + s] = val;
    }
}

// ---------------------------------------------------------------------------
// merge: persistent fp16 mma.sync m16n8k16, 2 CTAs/SM (N-half each),
// warp = 4j x 32n. hx/hy loaded DIRECTLY from global in the kt loop (no smem
// staging, no per-instance stage barrier). Partial buffers quad-buffered;
// block barrier only every 4 instances -> warps drift, epilogues decorrelate
// and overlap other warps' MMA phases.
// ---------------------------------------------------------------------------
#define SMB_B    0          // 65536 B
#define SMB_BM1  65536      // 512 B
#define SMB_BF   66048      // 2048 B
#define SMB_PT   68096      // [4 slot][4 nw][384] f32 = 24576 B
#define SMB_TOT  92672

#define N_ITILES 48
#define INSTANCES (2 * N_ITILES * 96)   // (half, tile) pairs = 9216
#define N_CTAS   296

__global__ __launch_bounds__(256, 2)
void merge_kernel(const float* __restrict__ Wm1, const float* __restrict__ bm1,
                  const float* __restrict__ Wm2)
{
    extern __shared__ __align__(16) char smem[];
    uint32_t* sBh  = (uint32_t*)(smem + SMB_B);
    float*    s_b1 = (float*)(smem + SMB_BM1);
    uint2*    s_bf = (uint2*)(smem + SMB_BF);

    const int tid  = threadIdx.x;
    const int wid  = tid >> 5;
    const int lane = tid & 31;
    const int qk   = lane & 3;
    const int qr   = lane >> 2;
    const int nw   = wid & 3;          // n-quarter of the half
    const int jw   = wid >> 2;         // j-half (4 j each)

    const int cta = blockIdx.x;
    const int hlf = cta & 1;
    const int h0  = hlf * 128;

    // ---- one-time: B-half (Wm1) as fp16 mma fragments (paired layout) ----
    for (int idx = tid; idx < 128 * 64; idx += 256) {
        const int n  = idx >> 6;
        const int f4 = idx & 63;
        float4 v = *(const float4*)(Wm1 + (size_t)(h0 + n) * HID + f4 * 4);
        uint32_t h2a = pack_h2(v.x, v.y);
        uint32_t h2b = pack_h2(v.z, v.w);
        const int nt = n >> 3, qr_l = n & 7, pr = nt >> 1, sub = nt & 1;
        #pragma unroll
        for (int e = 0; e < 2; e++) {
            const int p  = 2 * f4 + e;
            const int kt = p >> 3, w8 = p & 7;
            const int slot = (((kt * 8 + pr) * 32 + qr_l * 4 + (w8 & 3)) * 4)
                             + sub * 2 + (w8 >> 2);
            sBh[slot] = e ? h2b : h2a;
        }
    }
    if (tid < 128) s_b1[tid] = bm1[h0 + tid];
    {   // fold-B fragments: [8 kt2][32 lane]
        const int kt2 = tid >> 5, ln = tid & 31;
        const int fqk = ln & 3, fqr = ln >> 2;
        uint2 v = make_uint2(0u, 0u);
        if (fqr < 3) {
            const float* wsrc = Wm2 + (size_t)fqr * HID + h0 + kt2 * 16 + 2 * fqk;
            v.x = pack_h2(wsrc[0], wsrc[1]);
            v.y = pack_h2(wsrc[8], wsrc[9]);
        }
        s_bf[kt2 * 32 + ln] = v;
    }
    __syncthreads();

    // ---- persistent instance loop: barrier only every 4 instances ----
    int wcount = 0;
    for (int inst = cta; inst < INSTANCES; inst += N_CTAS, wcount++) {
        const int t  = inst >> 1;           // parity matches cta parity = hlf
        const int i0 = (t % N_ITILES) * 16;
        const int j0 = (t / N_ITILES) * 8;

        // accumulators initialized with bm1 (MMA accumulates on top)
        float d[4][4][4];    // [jj][ntl][frag]; global nt = 4*nw + ntl
        #pragma unroll
        for (int ntl = 0; ntl < 4; ntl++) {
            const float b0 = s_b1[(4 * nw + ntl) * 8 + qk * 2 + 0];
            const float b1 = s_b1[(4 * nw + ntl) * 8 + qk * 2 + 1];
            #pragma unroll
            for (int jj = 0; jj < 4; jj++) {
                d[jj][ntl][0] = b0; d[jj][ntl][1] = b1;
                d[jj][ntl][2] = b0; d[jj][ntl][3] = b1;
            }
        }

        // hx/hy straight from global (L1/L2-hot tiles, uint2 = LDG.64)
        const uint32_t* gx0 = g_hxh + (size_t)(i0 + qr) * 128;
        const uint32_t* gx1 = gx0 + 8 * 128;
        const uint32_t* gy  = g_hyh + (size_t)(j0 + jw * 4) * 128;
        const uint4*    bb  = (const uint4*)sBh + lane;

        #pragma unroll 2
        for (int kt = 0; kt < 16; kt++) {
            const int so = (kt * 4 + qk) * 2;
            const uint2 x0 = *(const uint2*)(gx0 + so);
            const uint2 x1 = *(const uint2*)(gx1 + so);
            const uint4 Ba = bb[(kt * 8 + 2 * nw) * 32];
            const uint4 Bb = bb[(kt * 8 + 2 * nw + 1) * 32];
            #pragma unroll
            for (int jj = 0; jj < 4; jj++) {
                const uint2 yu = *(const uint2*)(gy + jj * 128 + so);
                uint32_t a[4];
                a[0] = hmul2u(x0.x, yu.x);
                a[1] = hmul2u(x1.x, yu.x);
                a[2] = hmul2u(x0.y, yu.y);
                a[3] = hmul2u(x1.y, yu.y);
                MMA_F16(d[jj][0], a, Ba.x, Ba.y);
                MMA_F16(d[jj][1], a, Ba.z, Ba.w);
                MMA_F16(d[jj][2], a, Bb.x, Bb.y);
                MMA_F16(d[jj][3], a, Bb.z, Bb.w);
            }
        }

        // ---- epilogue: sin -> pack -> fold-MMA over warp's N=32 ----
        float* s_pt = (float*)(smem + SMB_PT) + (wcount & 3) * 1536;
        float* pp   = s_pt + nw * 384;
        #pragma unroll
        for (int jj = 0; jj < 4; jj++) {
            float fd[4] = {0.f, 0.f, 0.f, 0.f};
            #pragma unroll
            for (int e = 0; e < 2; e++) {
                const int kt2 = 2 * nw + e;
                uint32_t a[4];
                a[0] = pack_h2(__sinf(d[jj][2 * e][0]),     __sinf(d[jj][2 * e][1]));
                a[1] = pack_h2(__sinf(d[jj][2 * e][2]),     __sinf(d[jj][2 * e][3]));
                a[2] = pack_h2(__sinf(d[jj][2 * e + 1][0]), __sinf(d[jj][2 * e + 1][1]));
                a[3] = pack_h2(__sinf(d[jj][2 * e + 1][2]), __sinf(d[jj][2 * e + 1][3]));
                uint2 bf = s_bf[kt2 * 32 + lane];
                MMA_F16(fd, a, bf.x, bf.y);
            }
            const int jl = jw * 4 + jj;
            if (qk == 0) {
                pp[(jl * 16 + qr) * 3 + 0]     = fd[0];
                pp[(jl * 16 + qr) * 3 + 1]     = fd[1];
                pp[(jl * 16 + qr + 8) * 3 + 0] = fd[2];
                pp[(jl * 16 + qr + 8) * 3 + 1] = fd[3];
            } else if (qk == 1) {
                pp[(jl * 16 + qr) * 3 + 2]     = fd[0];
                pp[(jl * 16 + qr + 8) * 3 + 2] = fd[2];
            }
        }

        // ---- window close: combine the up-to-4 buffered instances ----
        const bool last = (inst + N_CTAS) >= INSTANCES;
        if ((wcount & 3) == 3 || last) {
            __syncthreads();   // all warps' partials for this window written
            const int wbase = wcount & ~3;
            #pragma unroll
            for (int s = 0; s <= 3; s++) {
                if (wbase + s > wcount) break;
                const int instS = cta + (wbase + s) * N_CTAS;
                const int tS  = instS >> 1;
                const int i0S = (tS % N_ITILES) * 16;
                const int j0S = (tS / N_ITILES) * 8;
                const float* sb = (const float*)(smem + SMB_PT) + s * 1536;
                for (int idx = tid; idx < 384; idx += 256) {
                    float v = sb[idx] + sb[384 + idx] + sb[768 + idx] + sb[1152 + idx];
                    const int c   = idx % 3;
                    const int rem = idx / 3;
                    const int i   = rem & 15;
                    const int j   = rem >> 4;
                    g_part[hlf][(size_t)c * NPIX + (size_t)(j0S + j) * HH + (i0S + i)] = v;
                }
            }
            __syncthreads();   // buffers free for next window
        }
    }
}

// ---------------------------------------------------------------------------
__global__ __launch_bounds__(256)
void final_kernel(const float* __restrict__ bm2, float* __restrict__ out)
{
    const int idx = blockIdx.x * 256 + threadIdx.x;   // float4 index
    if (idx < 3 * NPIX / 4) {
        const int c = idx / (NPIX / 4);
        const float bc = bm2[c];
        float4 a = ((const float4*)g_part[0])[idx];
        float4 b = ((const float4*)g_part[1])[idx];
        float4 o;
        o.x = __fdividef(1.0f, 1.0f + __expf(-(a.x + b.x + bc)));
        o.y = __fdividef(1.0f, 1.0f + __expf(-(a.y + b.y + bc)));
        o.z = __fdividef(1.0f, 1.0f + __expf(-(a.z + b.z + bc)));
        o.w = __fdividef(1.0f, 1.0f + __expf(-(a.w + b.w + bc)));
        ((float4*)out)[idx] = o;
    }
}

// ---------------------------------------------------------------------------
extern "C" void kernel_launch(void* const* d_in, const int* in_sizes, int n_in,
                              void* d_out, int out_size) {
    const float* x   = (const float*)d_in[0];
    const float* y   = (const float*)d_in[1];
    const float* Wbx = (const float*)d_in[2];
    const float* bbx = (const float*)d_in[3];
    const float* Wby = (const float*)d_in[4];
    const float* bby = (const float*)d_in[5];
    const float* Wp1 = (const float*)d_in[6];
    const float* bp1 = (const float*)d_in[7];
    const float* Wp2 = (const float*)d_in[8];
    const float* bp2 = (const float*)d_in[9];
    const float* Wm1 = (const float*)d_in[10];
    const float* bm1 = (const float*)d_in[11];
    const float* Wm2 = (const float*)d_in[12];
    const float* bm2 = (const float*)d_in[13];
    float* out = (float*)d_out;

    cudaFuncSetAttribute(merge_kernel,
                         cudaFuncAttributeMaxDynamicSharedMemorySize, SMB_TOT);

    branch_kernel<<<dim3(HH / 12, 2), 256>>>(x, y, Wbx, bbx, Wby, bby,
                                             Wp1, bp1, Wp2, bp2);
    merge_kernel<<<N_CTAS, 256, SMB_TOT>>>(Wm1, bm1, Wm2);
    final_kernel<<<(3 * NPIX / 4 + 255) / 256, 256>>>(bm2, out);
}

// round 17
// speedup vs baseline: 1.1029x; 1.1029x over previous
#include <cuda_runtime.h>
#include <cuda_fp16.h>
#include <cstdint>

#define HH   768
#define WW   768
#define HID  256
#define NPIX (HH*WW)

// ---------------- scratch ----------------
__device__ uint32_t g_hxh[HH * 128];        // interleaved half2 rows (branch out)
__device__ uint32_t g_hyh[WW * 128];
__device__ uint4    g_hxA[48 * 16 * 32];    // fragment-major hx: [itile][kt][lane]

// ---------------- helpers ----------------
__device__ __forceinline__ uint32_t pack_h2(float lo, float hi) {
    __half2 h = __floats2half2_rn(lo, hi);
    return *reinterpret_cast<uint32_t*>(&h);
}
__device__ __forceinline__ uint32_t hmul2u(uint32_t a, uint32_t b) {
    uint32_t d;
    asm("mul.f16x2 %0, %1, %2;" : "=r"(d) : "r"(a), "r"(b));
    return d;
}
__device__ __forceinline__ float fast_sin(float x) {
    const float INV_PI = 0.3183098861837907f;
    const float PI_HI  = 3.14159274101257324f;
    const float PI_LO  = -8.742277657347586e-8f;
    int   iq = __float2int_rn(x * INV_PI);
    float fq = (float)iq;
    float r  = fmaf(fq, -PI_HI, x);
    r        = fmaf(fq, -PI_LO, r);
    float r2 = r * r;
    float p  = fmaf(r2, 2.7183114939898219e-6f, -1.9839334836096632e-4f);
    p        = fmaf(r2, p, 8.3333293858894632e-3f);
    p        = fmaf(r2, p, -1.6666666641626524e-1f);
    p        = fmaf(r2 * r, p, r);
    return (iq & 1) ? -p : p;
}

#define MMA_F16(d, a, b0, b1) \
    asm volatile("mma.sync.aligned.m16n8k16.row.col.f32.f16.f16.f32 " \
        "{%0,%1,%2,%3}, {%4,%5,%6,%7}, {%8,%9}, {%0,%1,%2,%3};" \
        : "+f"((d)[0]), "+f"((d)[1]), "+f"((d)[2]), "+f"((d)[3]) \
        : "r"((a)[0]), "r"((a)[1]), "r"((a)[2]), "r"((a)[3]), \
          "r"(b0), "r"(b1))

#define QUAD_BAR(q) \
    asm volatile("bar.sync %0, 128;" :: "r"((q) + 1) : "memory")

// ---------------------------------------------------------------------------
// branch networks: 12 rows/block, 256 threads, grid (64, 2). unroll 8.
// ---------------------------------------------------------------------------
__global__ __launch_bounds__(256)
void branch_kernel(const float* __restrict__ x, const float* __restrict__ y,
                   const float* __restrict__ Wbx, const float* __restrict__ bbx,
                   const float* __restrict__ Wby, const float* __restrict__ bby,
                   const float* __restrict__ Wp1, const float* __restrict__ bp1,
                   const float* __restrict__ Wp2, const float* __restrict__ bp2)
{
    __shared__ float s0[12 * 256];
    __shared__ float s1[12 * 256];

    const int t  = threadIdx.x;
    const int br = blockIdx.y;
    const float* coord = br ? y   : x;
    const float* Wb    = br ? Wby : Wbx;
    const float* bb    = br ? bby : bbx;
    uint32_t*    outph = br ? g_hyh : g_hxh;
    const int r0 = blockIdx.x * 12;

    {
        float wv = Wb[t], bv = bb[t];
        #pragma unroll
        for (int r = 0; r < 12; r++)
            s0[r * 256 + t] = fast_sin(fmaf(coord[r0 + r], wv, bv));
    }
    __syncthreads();

    {
        float acc[12]; float b = bp1[t];
        #pragma unroll
        for (int r = 0; r < 12; r++) acc[r] = b;
        const float4* wrow = (const float4*)(Wp1 + (size_t)t * HID);
        #pragma unroll 8
        for (int k4 = 0; k4 < 64; k4++) {
            float4 w = wrow[k4];
            #pragma unroll
            for (int r = 0; r < 12; r++) {
                float4 h = *(const float4*)&s0[r * 256 + k4 * 4];
                acc[r] = fmaf(w.x, h.x, acc[r]); acc[r] = fmaf(w.y, h.y, acc[r]);
                acc[r] = fmaf(w.z, h.z, acc[r]); acc[r] = fmaf(w.w, h.w, acc[r]);
            }
        }
        #pragma unroll
        for (int r = 0; r < 12; r++) s1[r * 256 + t] = fast_sin(acc[r]);
    }
    __syncthreads();

    {
        float acc0[12], acc1[12];
        float b0 = bp2[t], b1 = bp2[t + 256];
        #pragma unroll
        for (int r = 0; r < 12; r++) { acc0[r] = b0; acc1[r] = b1; }
        const float4* w0row = (const float4*)(Wp2 + (size_t)t * HID);
        const float4* w1row = (const float4*)(Wp2 + (size_t)(t + 256) * HID);
        #pragma unroll 8
        for (int k4 = 0; k4 < 64; k4++) {
            float4 w0 = w0row[k4], w1 = w1row[k4];
            #pragma unroll
            for (int r = 0; r < 12; r++) {
                float4 h = *(const float4*)&s1[r * 256 + k4 * 4];
                acc0[r] = fmaf(w0.x, h.x, acc0[r]); acc0[r] = fmaf(w0.y, h.y, acc0[r]);
                acc0[r] = fmaf(w0.z, h.z, acc0[r]); acc0[r] = fmaf(w0.w, h.w, acc0[r]);
                acc1[r] = fmaf(w1.x, h.x, acc1[r]); acc1[r] = fmaf(w1.y, h.y, acc1[r]);
                acc1[r] = fmaf(w1.z, h.z, acc1[r]); acc1[r] = fmaf(w1.w, h.w, acc1[r]);
            }
        }
        #pragma unroll
        for (int r = 0; r < 12; r++)
            s0[r * 256 + t] = fast_sin(acc0[r]) + fast_sin(acc1[r]);
    }
    __syncthreads();

    for (int idx = t; idx < 12 * 64; idx += 256) {
        const int r = idx >> 6, s = idx & 63;
        const int n0 = (s >> 2) * 16 + (s & 3) * 2;
        const float* row = s0 + r * 256;
        uint2 val;
        val.x = pack_h2(row[n0],     row[n0 + 1]);
        val.y = pack_h2(row[n0 + 8], row[n0 + 9]);
        ((uint2*)outph)[(size_t)(r0 + r) * 64 + s] = val;
    }
}

// ---------------------------------------------------------------------------
// pack hx into fragment-major layout: g_hxA[itile][kt][lane] =
//   { row(i0+qr) u32[so], u32[so+1], row(i0+qr+8) u32[so], u32[so+1] },
//   lane = qr*4+qk, so = (kt*4+qk)*2.
// ---------------------------------------------------------------------------
__global__ __launch_bounds__(256)
void packA_kernel()
{
    const int id = blockIdx.x * 256 + threadIdx.x;
    if (id < 48 * 16 * 32) {
        const int lane  = id & 31;
        const int kt    = (id >> 5) & 15;
        const int itile = id >> 9;
        const int qr = lane >> 2, qk = lane & 3;
        const int so = (kt * 4 + qk) * 2;
        const uint32_t* r0 = g_hxh + (size_t)(itile * 16 + qr) * 128;
        const uint32_t* r1 = r0 + 8 * 128;
        g_hxA[id] = make_uint4(r0[so], r0[so + 1], r1[so], r1[so + 1]);
    }
}

// ---------------------------------------------------------------------------
// merge: persistent fp16 mma.sync m16n8k16, full-N B in smem, 512 threads,
// BARRIER-FREE main loop. Warp = 16i x 2j x quarter-N (d=64 regs).
// Quad q = warps {q, q+4, q+8, q+12} (one per SMSP) owns full N for its unit
// stream; combine via smem slot + 128-thread named barrier (double-buffered).
// Output written directly (bm2 + sigmoid fused).
// ---------------------------------------------------------------------------
#define SMB_B    0          // 131072 B
#define SMB_BM1  131072     // 1024 B
#define SMB_BF   132096     // 4096 B
#define SMB_PT   136192     // [4 quad][2 buf][4 m][96] f32 = 12288 B
#define SMB_TOT  148480

#define N_ITILES 48
#define UNITS    (N_ITILES * (WW / 2))   // 48 x 384 = 18432
#define STREAMS  (148 * 4)               // 592 quad-streams

__global__ __launch_bounds__(512, 1)
void merge_kernel(const float* __restrict__ Wm1, const float* __restrict__ bm1,
                  const float* __restrict__ Wm2, const float* __restrict__ bm2,
                  float* __restrict__ outg)
{
    extern __shared__ __align__(16) char smem[];
    uint32_t* sBh  = (uint32_t*)(smem + SMB_B);
    float*    s_b1 = (float*)(smem + SMB_BM1);
    uint2*    s_bf = (uint2*)(smem + SMB_BF);

    const int tid  = threadIdx.x;
    const int wid  = tid >> 5;
    const int lane = tid & 31;
    const int qk   = lane & 3;
    const int qr   = lane >> 2;
    const int q    = wid & 3;          // quad id == SMSP id of this warp
    const int m    = wid >> 2;         // N-quarter within quad
    const int g128 = m * 32 + lane;    // thread id within quad (0..127)

    const int cta = blockIdx.x;

    // ---- one-time: full B (Wm1) as fp16 mma fragments (paired layout) ----
    for (int idx = tid; idx < 256 * 64; idx += 512) {
        const int n  = idx >> 6;
        const int f4 = idx & 63;
        float4 v = *(const float4*)(Wm1 + (size_t)n * HID + f4 * 4);
        uint32_t h2a = pack_h2(v.x, v.y);
        uint32_t h2b = pack_h2(v.z, v.w);
        const int nt = n >> 3, qr_l = n & 7, pr = nt >> 1, sub = nt & 1;
        #pragma unroll
        for (int e = 0; e < 2; e++) {
            const int p  = 2 * f4 + e;
            const int kt = p >> 3, w8 = p & 7;
            const int slot = (((kt * 16 + pr) * 32 + qr_l * 4 + (w8 & 3)) * 4)
                             + sub * 2 + (w8 >> 2);
            sBh[slot] = e ? h2b : h2a;
        }
    }
    if (tid < 256) s_b1[tid] = bm1[tid];
    {   // fold-B fragments: [16 kt2][32 lane]
        const int kt2 = tid >> 5, ln = tid & 31;
        const int fqk = ln & 3, fqr = ln >> 2;
        uint2 v = make_uint2(0u, 0u);
        if (fqr < 3) {
            const float* wsrc = Wm2 + (size_t)fqr * HID + kt2 * 16 + 2 * fqk;
            v.x = pack_h2(wsrc[0], wsrc[1]);
            v.y = pack_h2(wsrc[8], wsrc[9]);
        }
        s_bf[kt2 * 32 + ln] = v;
    }
    __syncthreads();

    // per-warp bm1 bias values for its quarter (nt = m*8 + ntl)
    float bias[8][2];
    #pragma unroll
    for (int ntl = 0; ntl < 8; ntl++) {
        bias[ntl][0] = s_b1[(m * 8 + ntl) * 8 + qk * 2 + 0];
        bias[ntl][1] = s_b1[(m * 8 + ntl) * 8 + qk * 2 + 1];
    }
    // fold-B frags for this quarter (kt2 = m*4+e)
    uint2 bfr[4];
    #pragma unroll
    for (int e = 0; e < 4; e++) bfr[e] = s_bf[(m * 4 + e) * 32 + lane];

    float* const ptbase = (float*)(smem + SMB_PT) + q * 2 * 384;

    // ---- barrier-free persistent unit loop (per quad-stream) ----
    int k = 0;
    for (int unit = cta * 4 + q; unit < UNITS; unit += STREAMS, k++) {
        const int itile = unit % N_ITILES;
        const int i0    = itile * 16;
        const int j0    = (unit / N_ITILES) * 2;

        float d[2][8][4];
        #pragma unroll
        for (int ntl = 0; ntl < 8; ntl++) {
            #pragma unroll
            for (int jj = 0; jj < 2; jj++) {
                d[jj][ntl][0] = bias[ntl][0]; d[jj][ntl][1] = bias[ntl][1];
                d[jj][ntl][2] = bias[ntl][0]; d[jj][ntl][3] = bias[ntl][1];
            }
        }

        const uint4*    gxa = g_hxA + (size_t)itile * 512 + lane;
        const uint32_t* gy  = g_hyh + (size_t)j0 * 128;
        const uint4*    bb  = (const uint4*)sBh + lane;

        #pragma unroll 2
        for (int kt = 0; kt < 16; kt++) {
            const int so = (kt * 4 + qk) * 2;
            const uint4 hx4 = gxa[kt * 32];
            const uint2 y0 = *(const uint2*)(gy + so);
            const uint2 y1 = *(const uint2*)(gy + 128 + so);
            uint32_t a0[4], a1[4];
            a0[0] = hmul2u(hx4.x, y0.x); a0[1] = hmul2u(hx4.z, y0.x);
            a0[2] = hmul2u(hx4.y, y0.y); a0[3] = hmul2u(hx4.w, y0.y);
            a1[0] = hmul2u(hx4.x, y1.x); a1[1] = hmul2u(hx4.z, y1.x);
            a1[2] = hmul2u(hx4.y, y1.y); a1[3] = hmul2u(hx4.w, y1.y);
            uint4 Bv[4];
            #pragma unroll
            for (int p = 0; p < 4; p++)
                Bv[p] = bb[(kt * 16 + m * 4 + p) * 32];
            #pragma unroll
            for (int p = 0; p < 4; p++) {
                MMA_F16(d[0][2 * p],     a0, Bv[p].x, Bv[p].y);
                MMA_F16(d[0][2 * p + 1], a0, Bv[p].z, Bv[p].w);
                MMA_F16(d[1][2 * p],     a1, Bv[p].x, Bv[p].y);
                MMA_F16(d[1][2 * p + 1], a1, Bv[p].z, Bv[p].w);
            }
        }

        // ---- epilogue: sin -> pack -> fold-MMA over quarter-N ----
        float* ps = ptbase + (k & 1) * 384;   // [quad][buf][m][96]
        #pragma unroll
        for (int jj = 0; jj < 2; jj++) {
            float fd[4] = {0.f, 0.f, 0.f, 0.f};
            #pragma unroll
            for (int e = 0; e < 4; e++) {
                uint32_t a[4];
                a[0] = pack_h2(__sinf(d[jj][2 * e][0]),     __sinf(d[jj][2 * e][1]));
                a[1] = pack_h2(__sinf(d[jj][2 * e][2]),     __sinf(d[jj][2 * e][3]));
                a[2] = pack_h2(__sinf(d[jj][2 * e + 1][0]), __sinf(d[jj][2 * e + 1][1]));
                a[3] = pack_h2(__sinf(d[jj][2 * e + 1][2]), __sinf(d[jj][2 * e + 1][3]));
                MMA_F16(fd, a, bfr[e].x, bfr[e].y);
            }
            float* pm = ps + m * 96;
            if (qk == 0) {
                pm[(jj * 16 + qr) * 3 + 0]     = fd[0];
                pm[(jj * 16 + qr) * 3 + 1]     = fd[1];
                pm[(jj * 16 + qr + 8) * 3 + 0] = fd[2];
                pm[(jj * 16 + qr + 8) * 3 + 1] = fd[3];
            } else if (qk == 1) {
                pm[(jj * 16 + qr) * 3 + 2]     = fd[0];
                pm[(jj * 16 + qr + 8) * 3 + 2] = fd[2];
            }
        }
        QUAD_BAR(q);   // quad-local (128 threads), one per SMSP each

        // combine 4 quarters + bm2 + sigmoid -> out (direct)
        if (g128 < 96) {
            float v = ps[g128] + ps[96 + g128] + ps[192 + g128] + ps[288 + g128];
            const int c   = g128 % 3;
            const int rem = g128 / 3;
            const int i   = rem & 15;
            const int jj  = rem >> 4;
            v += bm2[c];
            outg[(size_t)c * NPIX + (size_t)(j0 + jj) * HH + (i0 + i)] =
                __fdividef(1.0f, 1.0f + __expf(-v));
        }
        // double-buffered slots: next write to this buf is 2 iterations away,
        // ordered by the intervening QUAD_BAR.
    }
}

// ---------------------------------------------------------------------------
extern "C" void kernel_launch(void* const* d_in, const int* in_sizes, int n_in,
                              void* d_out, int out_size) {
    const float* x   = (const float*)d_in[0];
    const float* y   = (const float*)d_in[1];
    const float* Wbx = (const float*)d_in[2];
    const float* bbx = (const float*)d_in[3];
    const float* Wby = (const float*)d_in[4];
    const float* bby = (const float*)d_in[5];
    const float* Wp1 = (const float*)d_in[6];
    const float* bp1 = (const float*)d_in[7];
    const float* Wp2 = (const float*)d_in[8];
    const float* bp2 = (const float*)d_in[9];
    const float* Wm1 = (const float*)d_in[10];
    const float* bm1 = (const float*)d_in[11];
    const float* Wm2 = (const float*)d_in[12];
    const float* bm2 = (const float*)d_in[13];
    float* out = (float*)d_out;

    cudaFuncSetAttribute(merge_kernel,
                         cudaFuncAttributeMaxDynamicSharedMemorySize, SMB_TOT);

    branch_kernel<<<dim3(HH / 12, 2), 256>>>(x, y, Wbx, bbx, Wby, bby,
                                             Wp1, bp1, Wp2, bp2);
    packA_kernel<<<(48 * 16 * 32 + 255) / 256, 256>>>();
    merge_kernel<<<148, 512, SMB_TOT>>>(Wm1, bm1, Wm2, bm2, out);
}